// round 10
// baseline (speedup 1.0000x reference)
#include <cuda_runtime.h>
#include <cuda_fp16.h>
#include <stdint.h>

#define D1    256
#define D2    256
#define ODIM  1024
#define BB    64
#define SS    128
#define KTOT  (D1 * D2)       // 65536

// ---------------- stage-1 (tp) config ----------------
#define NCH   4               // s-chunks of 32
#define CHS   32
#define PF2   132             // smem pitch (floats) for both F(128 d) and R(128 e)
#define CH_WORDS (CHS * PF2 * 2)            // F block + R block per chunk = 8448
#define SMEM1    (2 * CH_WORDS * 4)         // double-buffered: 67584 B

// ---------------- stage-2 mma config ----------------
#define KS2   18
#define NT2   128
#define KC2   32
#define STG   6
#define PRE   5

#define A2_BYTES  (64 * 80)
#define B2_BYTES  (128 * 144)
#define STAGE_B   (A2_BYTES + B2_BYTES)
#define SMEM2     (STG * STAGE_B)

// Device-global scratch
__device__ __half g_tp[(size_t)BB * KTOT];
__device__ float  g_partial[(size_t)KS2 * BB * ODIM];

// ---------------------------------------------------------------------------
// helpers
// ---------------------------------------------------------------------------
__device__ __forceinline__ uint32_t smem_u32(const void* p) {
    uint32_t a;
    asm("{ .reg .u64 t; cvta.to.shared.u64 t, %1; cvt.u32.u64 %0, t; }" : "=r"(a) : "l"(p));
    return a;
}
__device__ __forceinline__ uint32_t pack_h2(float lo, float hi) {
    uint32_t r;
    asm("cvt.rn.f16x2.f32 %0, %1, %2;" : "=r"(r) : "f"(hi), "f"(lo));
    return r;
}
__device__ __forceinline__ void cp16(uint32_t dst, const void* src) {
    asm volatile("cp.async.cg.shared.global [%0], [%1], 16;" :: "r"(dst), "l"(src));
}
__device__ __forceinline__ void hmma(float* c, const uint32_t* a, const uint32_t* b) {
    asm volatile(
        "mma.sync.aligned.m16n8k16.row.col.f32.f16.f16.f32 "
        "{%0,%1,%2,%3}, {%4,%5,%6,%7}, {%8,%9}, {%0,%1,%2,%3};"
        : "+f"(c[0]), "+f"(c[1]), "+f"(c[2]), "+f"(c[3])
        : "r"(a[0]), "r"(a[1]), "r"(a[2]), "r"(a[3]), "r"(b[0]), "r"(b[1]));
}

// ---------------------------------------------------------------------------
// Stage 1: tp[b, d, e] = sum_s F[fillers[b,s], d] * R[roles[b,s], e]
// grid (e-half=2, b=64, d-half=2) = 256 CTAs, 128 thr (4 warps), 2 CTAs/SM.
// CTA tile: 128 d x 128 e x 128 s. Warp tile 64d x 64e.
// Gather: cp.async fp32 rows, double-buffered s-chunks of 32; fp32->fp16 in
// the fragment path. Cross-CTA overlap hides gather/sync bubbles.
// ---------------------------------------------------------------------------
__global__ __launch_bounds__(128, 2) void tp_mma(
    const int*   __restrict__ fillers,
    const int*   __restrict__ roles,
    const float* __restrict__ ftab,
    const float* __restrict__ rtab)
{
    extern __shared__ float sm1[];
    __shared__ int s_fi[SS];
    __shared__ int s_ri[SS];

    const int b   = blockIdx.y;
    const int e0  = blockIdx.x * 128;
    const int d0  = blockIdx.z * 128;
    const int tid = threadIdx.x;
    const int wid  = tid >> 5;
    const int lane = tid & 31;

    s_fi[tid] = fillers[b * SS + tid];
    s_ri[tid] = roles[b * SS + tid];
    __syncthreads();

    // staging: 128 thr -> row rw 0..31 (4 thr/row), each thread loads
    // 8 x 16B chunks of F row + 8 x 16B chunks of R row (full 128 floats/row).
    const int c2 = tid & 3;
    const int rw = tid >> 2;

    auto load_chunk = [&](int ch) {
        if (ch < NCH) {
            float* dstF = sm1 + (ch & 1) * CH_WORDS;
            float* dstR = dstF + CHS * PF2;
            const int s = ch * CHS + rw;
            const float* fr = ftab + (size_t)s_fi[s] * D1 + d0;
            const float* rr = rtab + (size_t)s_ri[s] * D2 + e0;
            const uint32_t dF = smem_u32(dstF + rw * PF2);
            const uint32_t dR = smem_u32(dstR + rw * PF2);
            #pragma unroll
            for (int q = 0; q < 8; q++) {
                const int c = c2 + 4 * q;            // 16B chunk 0..31
                cp16(dF + c * 16, fr + c * 4);
                cp16(dR + c * 16, rr + c * 4);
            }
        }
        asm volatile("cp.async.commit_group;" ::: "memory");
    };

    // MMA mapping: 4 warps = 2 d-tiles x 2 e-tiles, warp tile 64d x 64e
    const int g  = lane >> 2;
    const int t  = lane & 3;
    const int mw = (wid & 1) * 64;
    const int nw = (wid >> 1) * 64;

    float acc[4][8][4];
    #pragma unroll
    for (int i = 0; i < 4; i++)
        #pragma unroll
        for (int j = 0; j < 8; j++)
            #pragma unroll
            for (int q = 0; q < 4; q++) acc[i][j][q] = 0.f;

    load_chunk(0);

    for (int ch = 0; ch < NCH; ch++) {
        load_chunk(ch + 1);
        asm volatile("cp.async.wait_group 1;" ::: "memory");
        __syncthreads();

        const float* sF = sm1 + (ch & 1) * CH_WORDS;
        const float* sR = sF + CHS * PF2;

        #pragma unroll
        for (int kc = 0; kc < 2; kc++) {
            const int k0 = kc * 16;
            uint32_t a[4][4];
            #pragma unroll
            for (int i = 0; i < 4; i++) {
                const int m = mw + 16 * i + g;
                const float* p0 = sF + (k0 + 2 * t)     * PF2;
                const float* p1 = sF + (k0 + 2 * t + 1) * PF2;
                const float* p2 = sF + (k0 + 2 * t + 8) * PF2;
                const float* p3 = sF + (k0 + 2 * t + 9) * PF2;
                a[i][0] = pack_h2(p0[m],     p1[m]);
                a[i][1] = pack_h2(p0[m + 8], p1[m + 8]);
                a[i][2] = pack_h2(p2[m],     p3[m]);
                a[i][3] = pack_h2(p2[m + 8], p3[m + 8]);
            }
            uint32_t bw[8][2];
            #pragma unroll
            for (int j = 0; j < 8; j++) {
                const int n = nw + 8 * j + g;
                const float* q0 = sR + (k0 + 2 * t)     * PF2;
                const float* q1 = sR + (k0 + 2 * t + 1) * PF2;
                const float* q2 = sR + (k0 + 2 * t + 8) * PF2;
                const float* q3 = sR + (k0 + 2 * t + 9) * PF2;
                bw[j][0] = pack_h2(q0[n], q1[n]);
                bw[j][1] = pack_h2(q2[n], q3[n]);
            }
            #pragma unroll
            for (int i = 0; i < 4; i++)
                #pragma unroll
                for (int j = 0; j < 8; j++)
                    hmma(acc[i][j], a[i], bw[j]);
        }
        __syncthreads();
    }

    // epilogue: g_tp[b][d][e] fp16
    __half* tpb = g_tp + (size_t)b * KTOT;
    #pragma unroll
    for (int i = 0; i < 4; i++) {
        const int d = d0 + mw + 16 * i + g;
        #pragma unroll
        for (int j = 0; j < 8; j++) {
            const int e = e0 + nw + 8 * j + 2 * t;
            *(uint32_t*)&tpb[(size_t)d * D2 + e] =
                pack_h2(acc[i][j][0], acc[i][j][1]);
            *(uint32_t*)&tpb[(size_t)(d + 8) * D2 + e] =
                pack_h2(acc[i][j][2], acc[i][j][3]);
        }
    }
}

// ---------------------------------------------------------------------------
// Stage 2: fp16 HMMA GEMM (at legacy-pipe floor). 8 n-tiles x 18 k-splits.
// ---------------------------------------------------------------------------
__global__ __launch_bounds__(128, 1) void gemm2_mma(const float* __restrict__ Wm)
{
    extern __shared__ char dsm[];
    const uint32_t smem_base = smem_u32(dsm);

    const int tid  = threadIdx.x;
    const int wid  = tid >> 5;
    const int lane = tid & 31;
    const int o0   = blockIdx.x * NT2;
    const int ks   = blockIdx.y;

    const int nstages = 113 + (ks < 14 ? 1 : 0);
    const size_t k_base = ((size_t)ks * 113 + (ks < 14 ? ks : 14)) * KC2;

    const int g  = lane >> 2;
    const int t  = lane & 3;
    const int n0 = wid * 32;

    const int c4 = tid & 3,  ra = tid >> 2;
    const int c8 = tid & 7,  rb = tid >> 3;

    float acc[4][4][4];
    #pragma unroll
    for (int i = 0; i < 4; i++)
        #pragma unroll
        for (int j = 0; j < 4; j++)
            #pragma unroll
            for (int q = 0; q < 4; q++) acc[i][j][q] = 0.f;

    auto load_stage = [&](int j) {
        if (j < nstages) {
            const uint32_t sb = smem_base + (uint32_t)(j % STG) * STAGE_B;
            const size_t kf = k_base + (size_t)j * KC2;
            #pragma unroll
            for (int p = 0; p < 2; p++) {
                const int row = ra + 32 * p;
                cp16(sb + (uint32_t)(row * 80 + c4 * 16),
                     g_tp + (size_t)row * KTOT + kf + c4 * 8);
            }
            #pragma unroll
            for (int p = 0; p < 8; p++) {
                const int row = rb + 16 * p;
                cp16(sb + (uint32_t)(A2_BYTES + row * 144 + c8 * 16),
                     Wm + (size_t)(o0 + row) * KTOT + kf + c8 * 4);
            }
        }
        asm volatile("cp.async.commit_group;" ::: "memory");
    };

    #pragma unroll
    for (int j = 0; j < PRE; j++) load_stage(j);

    for (int it = 0; it < nstages; it++) {
        asm volatile("cp.async.wait_group 4;" ::: "memory");
        __syncthreads();

        load_stage(it + PRE);

        const uint32_t* sAw  = (const uint32_t*)(dsm + (it % STG) * STAGE_B);
        const float*    sB32 = (const float*)   (dsm + (it % STG) * STAGE_B + A2_BYTES);

        #pragma unroll
        for (int kc = 0; kc < 2; kc++) {
            uint32_t a[4][4];
            #pragma unroll
            for (int i = 0; i < 4; i++) {
                const int base = (16 * i + g) * 20 + t + 8 * kc;
                a[i][0] = sAw[base];
                a[i][1] = sAw[base + 160];
                a[i][2] = sAw[base + 4];
                a[i][3] = sAw[base + 164];
            }
            uint32_t bf[4][2];
            #pragma unroll
            for (int j = 0; j < 4; j++) {
                const int fb = (n0 + 8 * j + g) * 36 + 2 * t + 16 * kc;
                bf[j][0] = pack_h2(sB32[fb],     sB32[fb + 1]);
                bf[j][1] = pack_h2(sB32[fb + 8], sB32[fb + 9]);
            }
            #pragma unroll
            for (int i = 0; i < 4; i++)
                #pragma unroll
                for (int j = 0; j < 4; j++)
                    hmma(acc[i][j], a[i], bf[j]);
        }
    }

    float* part = g_partial + (size_t)ks * (BB * ODIM);
    #pragma unroll
    for (int i = 0; i < 4; i++) {
        const int b_row = i * 16 + g;
        #pragma unroll
        for (int j = 0; j < 4; j++) {
            const int col = o0 + n0 + j * 8 + 2 * t;
            *(float2*)(part + (size_t)b_row * ODIM + col) =
                make_float2(acc[i][j][0], acc[i][j][1]);
            *(float2*)(part + (size_t)(b_row + 8) * ODIM + col) =
                make_float2(acc[i][j][2], acc[i][j][3]);
        }
    }
}

// ---------------------------------------------------------------------------
// Reduce: out[b][o] = bias[o] + sum_ks partial[ks][b][o]
// ---------------------------------------------------------------------------
__global__ __launch_bounds__(256) void reduce_kernel(
    const float* __restrict__ bias, float* __restrict__ out)
{
    const int idx = blockIdx.x * blockDim.x + threadIdx.x;
    const int o4  = (idx * 4) & (ODIM - 1);
    const int b   = (idx * 4) >> 10;

    float4 acc = *(const float4*)(bias + o4);
    const float* p = g_partial + (size_t)b * ODIM + o4;
    #pragma unroll
    for (int ks = 0; ks < KS2; ks++) {
        float4 v = *(const float4*)(p + (size_t)ks * (BB * ODIM));
        acc.x += v.x; acc.y += v.y; acc.z += v.z; acc.w += v.w;
    }
    *(float4*)(out + (size_t)b * ODIM + o4) = acc;
}

// ---------------------------------------------------------------------------
extern "C" void kernel_launch(void* const* d_in, const int* in_sizes, int n_in,
                              void* d_out, int out_size)
{
    const int*   fillers = (const int*)  d_in[0];
    const int*   roles   = (const int*)  d_in[1];
    const float* ftab    = (const float*)d_in[2];
    const float* rtab    = (const float*)d_in[3];
    const float* Wm      = (const float*)d_in[4];
    const float* bias    = (const float*)d_in[5];
    float* out = (float*)d_out;

    cudaFuncSetAttribute(tp_mma,    cudaFuncAttributeMaxDynamicSharedMemorySize, SMEM1);
    cudaFuncSetAttribute(gemm2_mma, cudaFuncAttributeMaxDynamicSharedMemorySize, SMEM2);

    tp_mma       <<<dim3(2, BB, 2), 128, SMEM1>>>(fillers, roles, ftab, rtab);
    gemm2_mma    <<<dim3(ODIM / NT2, KS2), 128, SMEM2>>>(Wm);
    reduce_kernel<<<(BB * ODIM / 4) / 256, 256>>>(bias, out);
}